// round 7
// baseline (speedup 1.0000x reference)
#include <cuda_runtime.h>

// StructuralLoss: predictions (64, 8192, 60) fp32 -> scalar.
// 20-float unit: bid_l=v[2l], ask_l=v[10+2l];
// viol = sum max(ask_l-ask_{l+1},0) + sum max(bid_{l+1}-bid_l,0) + max(bid0-ask0,0)
// out = (1/64) * sum over all units.
//
// Coalesced: 6 units = 30 float4 per warp "group"; lane l (<30) loads float4
// (group*30 + l). Cross-float4 terms via 2 warp shuffles. 4 groups unrolled
// per iteration (MLP=4), __launch_bounds__(256,8) for 8 CTAs/SM, and
// L2::256B prefetch-hinted non-coherent loads to widen DRAM bursts.

#define NBLOCKS 1184
#define NTHREADS 256
#define WARPS_PER_BLOCK (NTHREADS / 32)

__device__ float g_partials[NBLOCKS];
__device__ unsigned int g_ticket;   // zero-init; last block resets each run

__device__ __forceinline__ float4 ldg_nc256(const float4* p)
{
    float4 v;
    asm("ld.global.nc.L2::256B.v4.f32 {%0,%1,%2,%3}, [%4];"
        : "=f"(v.x), "=f"(v.y), "=f"(v.z), "=f"(v.w)
        : "l"(p));
    return v;
}

__global__ __launch_bounds__(NTHREADS, 8) void viol_kernel(
    const float4* __restrict__ pred4, int n_groups, float* __restrict__ out)
{
    const int lane   = threadIdx.x & 31;
    const int gwarp  = (blockIdx.x * WARPS_PER_BLOCK) + (threadIdx.x >> 5);
    const int twarps = NBLOCKS * WARPS_PER_BLOCK;
    const int j      = lane % 5;
    const bool valid = lane < 30;

    // Per-lane constant masks (hoisted out of the loop).
    const float sign = (j <= 1) ? 1.0f : -1.0f;
    const float c1 = (valid && j != 2) ? 1.0f : 0.0f;  // intra-float4 pair
    const float c2 = (valid && j != 4) ? 1.0f : 0.0f;  // cross-float4 pair
    const float cs = (valid && j == 0) ? 1.0f : 0.0f;  // spread bid0-ask0

    float acc = 0.0f;

    #define GROUP_TERMS(w)                                                 \
        do {                                                               \
            float n1 = __shfl_down_sync(0xffffffffu, (w).x, 1);            \
            float n2 = __shfl_down_sync(0xffffffffu, (w).z, 2);            \
            float d1 = sign * ((w).z - (w).x);                             \
            float d2 = sign * (n1 - (w).z);                                \
            float ds = (w).x - n2;                                         \
            acc = fmaf(c1, fmaxf(d1, 0.0f), acc);                          \
            acc = fmaf(c2, fmaxf(d2, 0.0f), acc);                          \
            acc = fmaf(cs, fmaxf(ds, 0.0f), acc);                          \
        } while (0)

    // 4 groups (24 units, 1920B) per warp-iteration -> 4 LDGs in flight.
    const int n_quads = n_groups >> 2;
    for (int q = gwarp; q < n_quads; q += twarps) {
        const float4* b = pred4 + ((long long)(4 * q) * 30 + lane);
        float4 w0 = make_float4(0.f, 0.f, 0.f, 0.f);
        float4 w1 = w0, w2 = w0, w3 = w0;
        if (valid) {
            w0 = ldg_nc256(b);
            w1 = ldg_nc256(b + 30);
            w2 = ldg_nc256(b + 60);
            w3 = ldg_nc256(b + 90);
        }
        GROUP_TERMS(w0);
        GROUP_TERMS(w1);
        GROUP_TERMS(w2);
        GROUP_TERMS(w3);
    }
    // Remainder groups (none for this shape: 262144 % 4 == 0).
    {
        int rem = n_groups & 3;
        int g = (n_quads << 2) + gwarp;
        if (gwarp < rem) {
            float4 w = make_float4(0.f, 0.f, 0.f, 0.f);
            if (valid) w = ldg_nc256(&pred4[(long long)g * 30 + lane]);
            GROUP_TERMS(w);
        }
    }
    #undef GROUP_TERMS

    // Deterministic block reduction.
    __shared__ float s[WARPS_PER_BLOCK];
    #pragma unroll
    for (int o = 16; o > 0; o >>= 1)
        acc += __shfl_down_sync(0xffffffffu, acc, o);
    if (lane == 0) s[threadIdx.x >> 5] = acc;
    __syncthreads();

    __shared__ bool s_is_last;
    if (threadIdx.x < 32) {
        float v = (threadIdx.x < WARPS_PER_BLOCK) ? s[threadIdx.x] : 0.0f;
        #pragma unroll
        for (int o = 16; o > 0; o >>= 1)
            v += __shfl_down_sync(0xffffffffu, v, o);
        if (threadIdx.x == 0) {
            g_partials[blockIdx.x] = v;
            __threadfence();
            unsigned int t = atomicAdd(&g_ticket, 1u);
            s_is_last = (t == NBLOCKS - 1);
        }
    }
    __syncthreads();

    // Last block finishes the reduction (deterministic order).
    if (s_is_last) {
        float facc = 0.0f;
        for (int i = threadIdx.x; i < NBLOCKS; i += NTHREADS)
            facc += g_partials[i];
        #pragma unroll
        for (int o = 16; o > 0; o >>= 1)
            facc += __shfl_down_sync(0xffffffffu, facc, o);
        __shared__ float fs[WARPS_PER_BLOCK];
        if ((threadIdx.x & 31) == 0) fs[threadIdx.x >> 5] = facc;
        __syncthreads();
        if (threadIdx.x == 0) {
            float t = 0.0f;
            #pragma unroll
            for (int i = 0; i < WARPS_PER_BLOCK; i++) t += fs[i];
            out[0] = t * (1.0f / 64.0f);
            g_ticket = 0;   // reset for next graph replay
        }
    }
}

extern "C" void kernel_launch(void* const* d_in, const int* in_sizes, int n_in,
                              void* d_out, int out_size)
{
    const float4* pred4 = (const float4*)d_in[0];
    float* out = (float*)d_out;
    int n_units  = in_sizes[0] / 20;   // 1,572,864
    int n_groups = n_units / 6;        // 262,144

    viol_kernel<<<NBLOCKS, NTHREADS>>>(pred4, n_groups, out);
}